// round 6
// baseline (speedup 1.0000x reference)
#include <cuda_runtime.h>

#define B_   16
#define T_   200
#define U1_  101
#define U_   100
#define V_   512
#define ND_  300          /* time-diagonals: d = t+u in [0, 299] */
#define DW_  104          /* padded diagonal width (u slots), 26 float4 */
#define DW4_ 26
#define PH_  152          /* diagonal rows staged per phase */
#define PAD_ 128          /* SMEM guard pad (floats): lanes 26-31 overread rows */
#define NEGV (-1e30f)

// Diagonal-major scratch: [b][d][u].  emitD is shifted: slot u+1 holds emit(t,u),
// so cell (d,u)'s deps (blank[t-1][u], emit[t][u-1]) BOTH sit at row d-1, slot u.
// Invalid slots are NEVER read unmasked: the DP staging loop substitutes NEGV
// based purely on coordinates, so garbage memory cannot affect results.
__device__ float g_blankD[B_ * ND_ * DW_];
__device__ float g_emitD [B_ * ND_ * DW_];
__device__ volatile float g_cost[B_];
__device__ int   g_done = 0;

// ---------------------------------------------------------------------------
// Kernel 1: per-row log-softmax stats. One warp per (b,t,u) row of V=512.
// Writes results straight into the diagonal-major layout (valid cells only).
// ---------------------------------------------------------------------------
__global__ void __launch_bounds__(256) rnnt_softmax_kernel(
    const float* __restrict__ acts,
    const int*   __restrict__ labels,
    const int*   __restrict__ label_lens)
{
    const int warp = (blockIdx.x * blockDim.x + threadIdx.x) >> 5;
    const int lane = threadIdx.x & 31;
    const int R = B_ * T_ * U1_;
    if (warp >= R) return;

    const int u = warp % U1_;
    const int t = (warp / U1_) % T_;
    const int b = warp / (T_ * U1_);

    const float4* __restrict__ p =
        reinterpret_cast<const float4*>(acts + (size_t)warp * V_);
    float4 v0 = __ldcs(p + lane);
    float4 v1 = __ldcs(p + lane + 32);
    float4 v2 = __ldcs(p + lane + 64);
    float4 v3 = __ldcs(p + lane + 96);

    // max reduce
    float m = fmaxf(fmaxf(fmaxf(v0.x, v0.y), fmaxf(v0.z, v0.w)),
                    fmaxf(fmaxf(v1.x, v1.y), fmaxf(v1.z, v1.w)));
    m = fmaxf(m, fmaxf(fmaxf(fmaxf(v2.x, v2.y), fmaxf(v2.z, v2.w)),
                       fmaxf(fmaxf(v3.x, v3.y), fmaxf(v3.z, v3.w))));
    #pragma unroll
    for (int off = 16; off > 0; off >>= 1)
        m = fmaxf(m, __shfl_xor_sync(0xffffffffu, m, off));

    // sum(exp(x - m)) reduce
    float s = __expf(v0.x - m) + __expf(v0.y - m) + __expf(v0.z - m) + __expf(v0.w - m)
            + __expf(v1.x - m) + __expf(v1.y - m) + __expf(v1.z - m) + __expf(v1.w - m)
            + __expf(v2.x - m) + __expf(v2.y - m) + __expf(v2.z - m) + __expf(v2.w - m)
            + __expf(v3.x - m) + __expf(v3.y - m) + __expf(v3.z - m) + __expf(v3.w - m);
    #pragma unroll
    for (int off = 16; off > 0; off >>= 1)
        s += __shfl_xor_sync(0xffffffffu, s, off);

    const float lse = m + __logf(s);

    const float blank_logit = __shfl_sync(0xffffffffu, v0.x, 0);

    int lbl = 0;
    if (u < U_) lbl = labels[b * U_ + u];
    const int j   = lbl >> 2;
    const int src = j & 31;
    const int k   = j >> 5;
    const int c   = lbl & 3;
    float4 sel = (k == 0) ? v0 : (k == 1) ? v1 : (k == 2) ? v2 : v3;
    float cand = (c == 0) ? sel.x : (c == 1) ? sel.y : (c == 2) ? sel.z : sel.w;
    const float label_logit = __shfl_sync(0xffffffffu, cand, src);

    if (lane == 0) {
        const int llen = label_lens[b];
        const int d    = t + u;
        const int base = b * ND_ * DW_ + d * DW_;
        g_blankD[base + u] = blank_logit - lse;
        if (u < llen)
            g_emitD[base + u + 1] = label_logit - lse;
    }
}

// ---------------------------------------------------------------------------
// Masked staging helper: substitute NEGV for invalid slots by coordinates.
// blank row r slot v holds blank(r-v, v): valid iff v<=100 && v<=r && r-v<=199.
// emit  row r slot v holds emit(r-v+1, v-1): valid iff 1<=v<=llen && v<=r+1
//                                                 && r-v+1<=199.
// ---------------------------------------------------------------------------
__device__ __forceinline__ void stage_row4(
    float4 xb, float4 xe, int r, int v0, int llen, float4* outB, float4* outE)
{
    float bb[4] = { xb.x, xb.y, xb.z, xb.w };
    float ee[4] = { xe.x, xe.y, xe.z, xe.w };
    #pragma unroll
    for (int k = 0; k < 4; ++k) {
        const int v = v0 + k;
        const bool bv = (v <= 100) && (v <= r) && (r - v <= 199);
        const bool ev = (v >= 1) && (v <= llen) && (v <= r + 1) && (r - v + 1 <= 199);
        bb[k] = bv ? bb[k] : NEGV;
        ee[k] = ev ? ee[k] : NEGV;
    }
    *outB = make_float4(bb[0], bb[1], bb[2], bb[3]);
    *outE = make_float4(ee[0], ee[1], ee[2], ee[3]);
}

// ---------------------------------------------------------------------------
// Kernel 2: forward DP — warp-synchronous wavefront, alpha carried in
// (m, s) form: alpha = m + log(s).  logaddexp costs ONE MUFU (exp) per cell;
// the recurrent m-chain is just FADD+FMNMX.  Renormalize every 32 diagonals.
// Per diagonal: 2 shfl + 2 LDS.128 + 4x{2 FADD, FMNMX, FSETP, 2 FSEL, FADD,
// MUFU, FFMA}.  Two staging phases; validity masked during staging.
// ---------------------------------------------------------------------------
__global__ void __launch_bounds__(128) rnnt_dp_kernel(
    const int* __restrict__ act_lens,
    const int* __restrict__ label_lens,
    float* __restrict__ out)
{
    extern __shared__ float sm[];
    float* Bs = sm;                 // PH_ * DW_
    float* Es = sm + PH_ * DW_;     // PH_ * DW_  (+ PAD_ guard after)

    const int b    = blockIdx.x;
    const int tid  = threadIdx.x;
    const int lane = tid & 31;

    const int alen  = act_lens[b];
    const int llen  = label_lens[b];
    const int dstar = (alen - 1) + llen;   // in [199, 299]

    const float4* gB = reinterpret_cast<const float4*>(g_blankD + b * ND_ * DW_);
    const float4* gE = reinterpret_cast<const float4*>(g_emitD  + b * ND_ * DW_);
    float4* sB = reinterpret_cast<float4*>(Bs);
    float4* sE = reinterpret_cast<float4*>(Es);

    // Stage phase 0: diagonal rows [0, PH_), masked.
    {
        const int n4 = PH_ * DW4_;         // 3952
        for (int i = tid; i < n4; i += 128) {
            const int r  = i / DW4_;
            const int v0 = (i - r * DW4_) * 4;
            stage_row4(gB[i], gE[i], r, v0, llen, &sB[i], &sE[i]);
        }
    }
    __syncthreads();

    float am[4], as[4];
    am[0] = (lane == 0) ? 0.0f : NEGV;
    am[1] = am[2] = am[3] = NEGV;
    as[0] = as[1] = as[2] = as[3] = 1.0f;
    const int ubase = lane << 2;

    if (tid < 32) {
        const int dend = (dstar < PH_) ? dstar : PH_;
        int off = ubase;
        for (int d = 1; d <= dend; ++d) {
            const float pm = __shfl_up_sync(0xffffffffu, am[3], 1);
            const float ps = __shfl_up_sync(0xffffffffu, as[3], 1);
            const float4 bl = *reinterpret_cast<const float4*>(Bs + off);
            const float4 em = *reinterpret_cast<const float4*>(Es + off);
            const float blv[4] = { bl.x, bl.y, bl.z, bl.w };
            const float emv[4] = { em.x, em.y, em.z, em.w };
            float cm[4] = { am[0], am[1], am[2], am[3] };
            float cs[4] = { as[0], as[1], as[2], as[3] };
            float lm[4] = { pm, am[0], am[1], am[2] };
            float ls[4] = { ps, as[0], as[1], as[2] };
            #pragma unroll
            for (int j = 0; j < 4; ++j) {
                const float mt = cm[j] + blv[j];     // top:  alpha(t-1,u)+blank
                const float ml = lm[j] + emv[j];     // left: alpha(t,u-1)+emit
                const bool  p  = mt >= ml;
                const float M  = fmaxf(mt, ml);
                const float dl = fminf(mt, ml) - M;  // <= 0
                const float e  = __expf(dl);
                const float sh = p ? cs[j] : ls[j];
                const float sl = p ? ls[j] : cs[j];
                am[j] = M;
                as[j] = fmaf(sl, e, sh);
            }
            off += DW_;
            if ((d & 31) == 0) {                     // renormalize
                #pragma unroll
                for (int j = 0; j < 4; ++j) { am[j] += __logf(as[j]); as[j] = 1.0f; }
            }
        }
    }
    __syncthreads();

    // Stage phase 1: diagonal rows [PH_, ND_-1), masked.
    {
        const int base4 = PH_ * DW4_;
        const int m4    = (ND_ - 1 - PH_) * DW4_;    // 147*26
        for (int i = tid; i < m4; i += 128) {
            const int r  = PH_ + i / DW4_;
            const int v0 = (i - (i / DW4_) * DW4_) * 4;
            stage_row4(gB[base4 + i], gE[base4 + i], r, v0, llen, &sB[i], &sE[i]);
        }
    }
    __syncthreads();

    if (tid < 32) {
        int off = ubase;
        for (int d = PH_ + 1; d <= dstar; ++d) {
            const float pm = __shfl_up_sync(0xffffffffu, am[3], 1);
            const float ps = __shfl_up_sync(0xffffffffu, as[3], 1);
            const float4 bl = *reinterpret_cast<const float4*>(Bs + off);
            const float4 em = *reinterpret_cast<const float4*>(Es + off);
            const float blv[4] = { bl.x, bl.y, bl.z, bl.w };
            const float emv[4] = { em.x, em.y, em.z, em.w };
            float cm[4] = { am[0], am[1], am[2], am[3] };
            float cs[4] = { as[0], as[1], as[2], as[3] };
            float lm[4] = { pm, am[0], am[1], am[2] };
            float ls[4] = { ps, as[0], as[1], as[2] };
            #pragma unroll
            for (int j = 0; j < 4; ++j) {
                const float mt = cm[j] + blv[j];
                const float ml = lm[j] + emv[j];
                const bool  p  = mt >= ml;
                const float M  = fmaxf(mt, ml);
                const float dl = fminf(mt, ml) - M;
                const float e  = __expf(dl);
                const float sh = p ? cs[j] : ls[j];
                const float sl = p ? ls[j] : cs[j];
                am[j] = M;
                as[j] = fmaf(sl, e, sh);
            }
            off += DW_;
            if ((d & 31) == 0) {
                #pragma unroll
                for (int j = 0; j < 4; ++j) { am[j] += __logf(as[j]); as[j] = 1.0f; }
            }
        }

        // alpha(alen-1, llen) = m + log(s) at slot llen.
        const int slot = llen & 3;
        float rm = am[slot <= 1 ? (slot == 0 ? 0 : 1) : (slot == 2 ? 2 : 3)];
        float rs = as[slot <= 1 ? (slot == 0 ? 0 : 1) : (slot == 2 ? 2 : 3)];
        rm = __shfl_sync(0xffffffffu, rm, llen >> 2);
        rs = __shfl_sync(0xffffffffu, rs, llen >> 2);
        if (lane == 0) {
            const float alpha = rm + __logf(rs);
            const float fb = g_blankD[b * ND_ * DW_ + dstar * DW_ + llen];
            g_cost[b] = -(alpha + fb);
            __threadfence();
            const int prev = atomicAdd(&g_done, 1);
            if (prev == B_ - 1) {
                __threadfence();
                float s = 0.0f;
                #pragma unroll
                for (int i = 0; i < B_; ++i) s += g_cost[i];
                out[0] = s / (float)B_;
                g_done = 0;            // reset for next graph replay
            }
        }
    }
}

// ---------------------------------------------------------------------------
extern "C" void kernel_launch(void* const* d_in, const int* in_sizes, int n_in,
                              void* d_out, int out_size)
{
    const float* acts       = (const float*)d_in[0];
    const int*   labels     = (const int*)  d_in[1];
    const int*   act_lens   = (const int*)  d_in[2];
    const int*   label_lens = (const int*)  d_in[3];
    float*       out        = (float*)      d_out;

    // Kernel 1: log-softmax stats.
    const int rows   = B_ * T_ * U1_;
    const int wpb    = 8;
    const int blocks = (rows + wpb - 1) / wpb;
    rnnt_softmax_kernel<<<blocks, wpb * 32>>>(acts, labels, label_lens);

    // Kernel 2: DP + finalize (validity masking folded into staging).
    const size_t smemBytes =
        (size_t)(2 * PH_ * DW_ + PAD_) * sizeof(float);   // 126,976 B
    cudaFuncSetAttribute(rnnt_dp_kernel,
                         cudaFuncAttributeMaxDynamicSharedMemorySize,
                         (int)smemBytes);
    rnnt_dp_kernel<<<B_, 128, smemBytes>>>(act_lens, label_lens, out);
}

// round 10
// speedup vs baseline: 1.0493x; 1.0493x over previous
#include <cuda_runtime.h>

#define B_   16
#define T_   200
#define U1_  101
#define U_   100
#define V_   512
#define ND_  300          /* time-diagonals: d = t+u in [0, 299] */
#define DW_  104          /* padded diagonal width (u slots), 26 float4 */
#define DW4_ 26
#define PH_  152          /* diagonal rows staged per phase */
#define PAD_ 128          /* SMEM guard pad (floats): lanes 26-31 overread rows */
#define NEGV (-1e30f)

// Diagonal-major scratch: [b][d][u].  emitD is shifted: slot u+1 holds emit(t,u),
// so cell (d,u)'s deps (blank[t-1][u], emit[t][u-1]) BOTH sit at row d-1, slot u.
// Slots outside the live region (t>=alen or u>llen) hold STALE GARBAGE —
// the DP staging mask replaces them with NEGV by pure coordinate tests, so
// garbage (even NaN) can never influence the result.
__device__ float g_blankD[B_ * ND_ * DW_];
__device__ float g_emitD [B_ * ND_ * DW_];
__device__ volatile float g_cost[B_];
__device__ int   g_done = 0;

// ---------------------------------------------------------------------------
// Kernel 1: per-row log-softmax stats. One warp per (b,t,u) row of V=512.
// Only live rows (t < alen, u <= llen) are read: ~34% DRAM traffic saved.
// ---------------------------------------------------------------------------
__global__ void __launch_bounds__(256) rnnt_softmax_kernel(
    const float* __restrict__ acts,
    const int*   __restrict__ labels,
    const int*   __restrict__ act_lens,
    const int*   __restrict__ label_lens)
{
    const int warp = (blockIdx.x * blockDim.x + threadIdx.x) >> 5;
    const int lane = threadIdx.x & 31;
    const int R = B_ * T_ * U1_;
    if (warp >= R) return;

    const int u = warp % U1_;
    const int t = (warp / U1_) % T_;
    const int b = warp / (T_ * U1_);

    // Early out for rows the DP can never use (uniform across the warp).
    const int alen = act_lens[b];
    const int llen = label_lens[b];
    if (t >= alen || u > llen) return;

    const float4* __restrict__ p =
        reinterpret_cast<const float4*>(acts + (size_t)warp * V_);
    float4 v0 = __ldcs(p + lane);
    float4 v1 = __ldcs(p + lane + 32);
    float4 v2 = __ldcs(p + lane + 64);
    float4 v3 = __ldcs(p + lane + 96);

    // max reduce
    float m = fmaxf(fmaxf(fmaxf(v0.x, v0.y), fmaxf(v0.z, v0.w)),
                    fmaxf(fmaxf(v1.x, v1.y), fmaxf(v1.z, v1.w)));
    m = fmaxf(m, fmaxf(fmaxf(fmaxf(v2.x, v2.y), fmaxf(v2.z, v2.w)),
                       fmaxf(fmaxf(v3.x, v3.y), fmaxf(v3.z, v3.w))));
    #pragma unroll
    for (int off = 16; off > 0; off >>= 1)
        m = fmaxf(m, __shfl_xor_sync(0xffffffffu, m, off));

    // sum(exp(x - m)) reduce
    float s = __expf(v0.x - m) + __expf(v0.y - m) + __expf(v0.z - m) + __expf(v0.w - m)
            + __expf(v1.x - m) + __expf(v1.y - m) + __expf(v1.z - m) + __expf(v1.w - m)
            + __expf(v2.x - m) + __expf(v2.y - m) + __expf(v2.z - m) + __expf(v2.w - m)
            + __expf(v3.x - m) + __expf(v3.y - m) + __expf(v3.z - m) + __expf(v3.w - m);
    #pragma unroll
    for (int off = 16; off > 0; off >>= 1)
        s += __shfl_xor_sync(0xffffffffu, s, off);

    const float lse = m + __logf(s);

    const float blank_logit = __shfl_sync(0xffffffffu, v0.x, 0);

    int lbl = 0;
    if (u < U_) lbl = labels[b * U_ + u];
    const int j   = lbl >> 2;
    const int src = j & 31;
    const int k   = j >> 5;
    const int c   = lbl & 3;
    float4 sel = (k == 0) ? v0 : (k == 1) ? v1 : (k == 2) ? v2 : v3;
    float cand = (c == 0) ? sel.x : (c == 1) ? sel.y : (c == 2) ? sel.z : sel.w;
    const float label_logit = __shfl_sync(0xffffffffu, cand, src);

    if (lane == 0) {
        const int d    = t + u;
        const int base = b * ND_ * DW_ + d * DW_;
        g_blankD[base + u] = blank_logit - lse;
        if (u < llen)
            g_emitD[base + u + 1] = label_logit - lse;
    }
}

// ---------------------------------------------------------------------------
// Masked staging: substitute NEGV for slots not computed by the softmax
// kernel, decided purely by coordinates (so stale/NaN memory is harmless).
// blank row r slot v holds blank(r-v, v):   valid iff v<=llen && v<=r
//                                             && r-v <= alen-1.
// emit  row r slot v holds emit(r-v+1,v-1): valid iff 1<=v<=llen && v<=r+1
//                                             && r-v+1 <= alen-1.
// ---------------------------------------------------------------------------
__device__ __forceinline__ void stage_row4(
    float4 xb, float4 xe, int r, int v0, int alen, int llen,
    float4* outB, float4* outE)
{
    float bb[4] = { xb.x, xb.y, xb.z, xb.w };
    float ee[4] = { xe.x, xe.y, xe.z, xe.w };
    #pragma unroll
    for (int k = 0; k < 4; ++k) {
        const int v = v0 + k;
        const bool bv = (v <= llen) && (v <= r)     && (r - v     <= alen - 1);
        const bool ev = (v >= 1) && (v <= llen) && (v <= r + 1) && (r - v + 1 <= alen - 1);
        bb[k] = bv ? bb[k] : NEGV;
        ee[k] = ev ? ee[k] : NEGV;
    }
    *outB = make_float4(bb[0], bb[1], bb[2], bb[3]);
    *outE = make_float4(ee[0], ee[1], ee[2], ee[3]);
}

// ---------------------------------------------------------------------------
// Kernel 2: forward DP — warp-synchronous wavefront over diag-major SMEM.
// R5 arithmetic (one shfl, plain logaddexp): the (m,s)-carry variant measured
// SLOWER (extra shfl + select network beat the saved log).
// Per diagonal: 1 shfl + 2 LDS.128 + branch-free logaddexp x4.
// ---------------------------------------------------------------------------
__global__ void __launch_bounds__(128) rnnt_dp_kernel(
    const int* __restrict__ act_lens,
    const int* __restrict__ label_lens,
    float* __restrict__ out)
{
    extern __shared__ float sm[];
    float* Bs = sm;                 // PH_ * DW_
    float* Es = sm + PH_ * DW_;     // PH_ * DW_  (+ PAD_ guard after)

    const int b    = blockIdx.x;
    const int tid  = threadIdx.x;
    const int lane = tid & 31;

    const int alen  = act_lens[b];
    const int llen  = label_lens[b];
    const int dstar = (alen - 1) + llen;   // in [199, 299]

    const float4* gB = reinterpret_cast<const float4*>(g_blankD + b * ND_ * DW_);
    const float4* gE = reinterpret_cast<const float4*>(g_emitD  + b * ND_ * DW_);
    float4* sB = reinterpret_cast<float4*>(Bs);
    float4* sE = reinterpret_cast<float4*>(Es);

    // Stage phase 0: diagonal rows [0, PH_), masked.
    {
        const int n4 = PH_ * DW4_;         // 3952
        for (int i = tid; i < n4; i += 128) {
            const int r  = i / DW4_;
            const int v0 = (i - r * DW4_) * 4;
            stage_row4(gB[i], gE[i], r, v0, alen, llen, &sB[i], &sE[i]);
        }
    }
    __syncthreads();

    float a0 = 0.f, a1 = NEGV, a2 = NEGV, a3 = NEGV;
    const int ubase = lane << 2;

    if (tid < 32) {
        a0 = (lane == 0) ? 0.0f : NEGV;
        const int dend = (dstar < PH_) ? dstar : PH_;
        int off = ubase;
        for (int d = 1; d <= dend; ++d) {
            const float am1 = __shfl_up_sync(0xffffffffu, a3, 1);
            const float4 bl = *reinterpret_cast<const float4*>(Bs + off);
            const float4 em = *reinterpret_cast<const float4*>(Es + off);
            float ac[4] = { a0, a1, a2, a3 };
            float ap[4] = { am1, a0, a1, a2 };
            const float blv[4] = { bl.x, bl.y, bl.z, bl.w };
            const float emv[4] = { em.x, em.y, em.z, em.w };
            float na[4];
            #pragma unroll
            for (int j = 0; j < 4; ++j) {
                const float top  = ac[j] + blv[j];
                const float left = ap[j] + emv[j];
                const float mx = fmaxf(top, left);
                const float mn = fminf(top, left);
                na[j] = mx + __logf(1.0f + __expf(mn - mx));
            }
            a0 = na[0]; a1 = na[1]; a2 = na[2]; a3 = na[3];
            off += DW_;
        }
    }
    __syncthreads();

    // Stage phase 1: diagonal rows [PH_, ND_-1), masked.
    {
        const int base4 = PH_ * DW4_;
        const int m4    = (ND_ - 1 - PH_) * DW4_;    // 147*26
        for (int i = tid; i < m4; i += 128) {
            const int rr = i / DW4_;
            const int r  = PH_ + rr;
            const int v0 = (i - rr * DW4_) * 4;
            stage_row4(gB[base4 + i], gE[base4 + i], r, v0, alen, llen,
                       &sB[i], &sE[i]);
        }
    }
    __syncthreads();

    if (tid < 32) {
        int off = ubase;
        for (int d = PH_ + 1; d <= dstar; ++d) {
            const float am1 = __shfl_up_sync(0xffffffffu, a3, 1);
            const float4 bl = *reinterpret_cast<const float4*>(Bs + off);
            const float4 em = *reinterpret_cast<const float4*>(Es + off);
            float ac[4] = { a0, a1, a2, a3 };
            float ap[4] = { am1, a0, a1, a2 };
            const float blv[4] = { bl.x, bl.y, bl.z, bl.w };
            const float emv[4] = { em.x, em.y, em.z, em.w };
            float na[4];
            #pragma unroll
            for (int j = 0; j < 4; ++j) {
                const float top  = ac[j] + blv[j];
                const float left = ap[j] + emv[j];
                const float mx = fmaxf(top, left);
                const float mn = fminf(top, left);
                na[j] = mx + __logf(1.0f + __expf(mn - mx));
            }
            a0 = na[0]; a1 = na[1]; a2 = na[2]; a3 = na[3];
            off += DW_;
        }

        // Extract alpha(alen-1, llen) and final blank from gmem row dstar.
        const int slot = llen & 3;
        float r = (slot == 0) ? a0 : (slot == 1) ? a1 : (slot == 2) ? a2 : a3;
        r = __shfl_sync(0xffffffffu, r, llen >> 2);
        if (lane == 0) {
            const float fb = g_blankD[b * ND_ * DW_ + dstar * DW_ + llen];
            g_cost[b] = -(r + fb);
            __threadfence();
            const int prev = atomicAdd(&g_done, 1);
            if (prev == B_ - 1) {
                __threadfence();
                float s = 0.0f;
                #pragma unroll
                for (int i = 0; i < B_; ++i) s += g_cost[i];
                out[0] = s / (float)B_;
                g_done = 0;            // reset for next graph replay
            }
        }
    }
}

// ---------------------------------------------------------------------------
extern "C" void kernel_launch(void* const* d_in, const int* in_sizes, int n_in,
                              void* d_out, int out_size)
{
    const float* acts       = (const float*)d_in[0];
    const int*   labels     = (const int*)  d_in[1];
    const int*   act_lens   = (const int*)  d_in[2];
    const int*   label_lens = (const int*)  d_in[3];
    float*       out        = (float*)      d_out;

    // Kernel 1: log-softmax stats over live rows only.
    const int rows   = B_ * T_ * U1_;
    const int wpb    = 8;
    const int blocks = (rows + wpb - 1) / wpb;
    rnnt_softmax_kernel<<<blocks, wpb * 32>>>(acts, labels, act_lens, label_lens);

    // Kernel 2: DP + finalize (validity masking folded into staging).
    const size_t smemBytes =
        (size_t)(2 * PH_ * DW_ + PAD_) * sizeof(float);   // 126,976 B
    cudaFuncSetAttribute(rnnt_dp_kernel,
                         cudaFuncAttributeMaxDynamicSharedMemorySize,
                         (int)smemBytes);
    rnnt_dp_kernel<<<B_, 128, smemBytes>>>(act_lens, label_lens, out);
}

// round 13
// speedup vs baseline: 1.2424x; 1.1841x over previous
#include <cuda_runtime.h>

#define B_   16
#define T_   200
#define U1_  101
#define U_   100
#define V_   512
#define ND_  300          /* time-diagonals: d = t+u in [0, 299] */
#define DW_  104          /* padded diagonal width (u slots), 26 float4 */
#define DW4_ 26
#define PH_  152          /* diagonal rows staged per phase */
#define PAD_ 128          /* SMEM guard pad (floats): prefetch + lane overread */
#define NEGV   (-1e30f)
#define LOG2E_ 1.4426950408889634f
#define LN2_   0.6931471805599453f

// Diagonal-major scratch in LOG2 DOMAIN: [b][d][u].  emitD is shifted: slot
// u+1 holds emit(t,u), so cell (d,u)'s deps (blank[t-1][u], emit[t][u-1])
// BOTH sit at row d-1, slot u.  Dead slots hold stale garbage; the DP staging
// mask replaces them with NEGV by pure coordinate tests.
__device__ float g_blankD[B_ * ND_ * DW_];
__device__ float g_emitD [B_ * ND_ * DW_];
__device__ volatile float g_cost[B_];
__device__ int   g_done = 0;

__device__ __forceinline__ float ex2f_(float x) {
    float r; asm("ex2.approx.ftz.f32 %0, %1;" : "=f"(r) : "f"(x)); return r;
}
__device__ __forceinline__ float lg2f_(float x) {
    float r; asm("lg2.approx.ftz.f32 %0, %1;" : "=f"(r) : "f"(x)); return r;
}

// ---------------------------------------------------------------------------
// Kernel 1: per-row log-softmax stats. One warp per (b,t,u) row of V=512.
// Only live rows (t < alen, u <= llen) are read.
// Writes RAW (natural-log) values; staging converts to log2 domain.
// ---------------------------------------------------------------------------
__global__ void __launch_bounds__(256) rnnt_softmax_kernel(
    const float* __restrict__ acts,
    const int*   __restrict__ labels,
    const int*   __restrict__ act_lens,
    const int*   __restrict__ label_lens)
{
    const int warp = (blockIdx.x * blockDim.x + threadIdx.x) >> 5;
    const int lane = threadIdx.x & 31;
    const int R = B_ * T_ * U1_;
    if (warp >= R) return;

    const int u = warp % U1_;
    const int t = (warp / U1_) % T_;
    const int b = warp / (T_ * U1_);

    const int alen = act_lens[b];
    const int llen = label_lens[b];
    if (t >= alen || u > llen) return;

    const float4* __restrict__ p =
        reinterpret_cast<const float4*>(acts + (size_t)warp * V_);
    float4 v0 = __ldcs(p + lane);
    float4 v1 = __ldcs(p + lane + 32);
    float4 v2 = __ldcs(p + lane + 64);
    float4 v3 = __ldcs(p + lane + 96);

    float m = fmaxf(fmaxf(fmaxf(v0.x, v0.y), fmaxf(v0.z, v0.w)),
                    fmaxf(fmaxf(v1.x, v1.y), fmaxf(v1.z, v1.w)));
    m = fmaxf(m, fmaxf(fmaxf(fmaxf(v2.x, v2.y), fmaxf(v2.z, v2.w)),
                       fmaxf(fmaxf(v3.x, v3.y), fmaxf(v3.z, v3.w))));
    #pragma unroll
    for (int off = 16; off > 0; off >>= 1)
        m = fmaxf(m, __shfl_xor_sync(0xffffffffu, m, off));

    float s = __expf(v0.x - m) + __expf(v0.y - m) + __expf(v0.z - m) + __expf(v0.w - m)
            + __expf(v1.x - m) + __expf(v1.y - m) + __expf(v1.z - m) + __expf(v1.w - m)
            + __expf(v2.x - m) + __expf(v2.y - m) + __expf(v2.z - m) + __expf(v2.w - m)
            + __expf(v3.x - m) + __expf(v3.y - m) + __expf(v3.z - m) + __expf(v3.w - m);
    #pragma unroll
    for (int off = 16; off > 0; off >>= 1)
        s += __shfl_xor_sync(0xffffffffu, s, off);

    const float lse = m + __logf(s);
    const float blank_logit = __shfl_sync(0xffffffffu, v0.x, 0);

    int lbl = 0;
    if (u < U_) lbl = labels[b * U_ + u];
    const int j   = lbl >> 2;
    const int src = j & 31;
    const int k   = j >> 5;
    const int c   = lbl & 3;
    float4 sel = (k == 0) ? v0 : (k == 1) ? v1 : (k == 2) ? v2 : v3;
    float cand = (c == 0) ? sel.x : (c == 1) ? sel.y : (c == 2) ? sel.z : sel.w;
    const float label_logit = __shfl_sync(0xffffffffu, cand, src);

    if (lane == 0) {
        const int d    = t + u;
        const int base = b * ND_ * DW_ + d * DW_;
        g_blankD[base + u] = blank_logit - lse;
        if (u < llen)
            g_emitD[base + u + 1] = label_logit - lse;
    }
}

// ---------------------------------------------------------------------------
// Masked staging: NEGV for coordinate-invalid slots (stale/NaN memory can
// never leak), and CONVERT valid values to log2 domain (x * log2e).
// blank row r slot v = blank(r-v, v):   valid iff v<=llen && v<=r && r-v<alen.
// emit  row r slot v = emit(r-v+1,v-1): valid iff 1<=v<=llen && v<=r+1
//                                              && r-v+1 < alen.
// ---------------------------------------------------------------------------
__device__ __forceinline__ void stage_row4(
    float4 xb, float4 xe, int r, int v0, int alen, int llen,
    float4* outB, float4* outE)
{
    float bb[4] = { xb.x, xb.y, xb.z, xb.w };
    float ee[4] = { xe.x, xe.y, xe.z, xe.w };
    #pragma unroll
    for (int k = 0; k < 4; ++k) {
        const int v = v0 + k;
        const bool bv = (v <= llen) && (v <= r)     && (r - v     <= alen - 1);
        const bool ev = (v >= 1) && (v <= llen) && (v <= r + 1) && (r - v + 1 <= alen - 1);
        bb[k] = bv ? (bb[k] * LOG2E_) : NEGV;
        ee[k] = ev ? (ee[k] * LOG2E_) : NEGV;
    }
    *outB = make_float4(bb[0], bb[1], bb[2], bb[3]);
    *outE = make_float4(ee[0], ee[1], ee[2], ee[3]);
}

// ---------------------------------------------------------------------------
// Kernel 2: forward DP — warp-synchronous wavefront in LOG2 domain.
// Lane L holds alpha2 (= alpha*log2e) for u = 4L..4L+3 in registers.
// Per diagonal: 1 shfl + 2 prefetched LDS.128 + phase-grouped arithmetic so
// the 4 MUFU chains pipeline instead of serializing.
// ---------------------------------------------------------------------------
__global__ void __launch_bounds__(128, 1) rnnt_dp_kernel(
    const int* __restrict__ act_lens,
    const int* __restrict__ label_lens,
    float* __restrict__ out)
{
    extern __shared__ float sm[];
    float* Bs = sm;                 // PH_ * DW_
    float* Es = sm + PH_ * DW_;     // PH_ * DW_  (+ PAD_ guard after)

    const int b    = blockIdx.x;
    const int tid  = threadIdx.x;
    const int lane = tid & 31;

    const int alen  = act_lens[b];
    const int llen  = label_lens[b];
    const int dstar = (alen - 1) + llen;   // in [199, 299]

    const float4* gB = reinterpret_cast<const float4*>(g_blankD + b * ND_ * DW_);
    const float4* gE = reinterpret_cast<const float4*>(g_emitD  + b * ND_ * DW_);
    float4* sB = reinterpret_cast<float4*>(Bs);
    float4* sE = reinterpret_cast<float4*>(Es);

    // Stage phase 0: diagonal rows [0, PH_), masked + log2-scaled.
    {
        const int n4 = PH_ * DW4_;         // 3952
        for (int i = tid; i < n4; i += 128) {
            const int r  = i / DW4_;
            const int v0 = (i - r * DW4_) * 4;
            stage_row4(gB[i], gE[i], r, v0, alen, llen, &sB[i], &sE[i]);
        }
    }
    __syncthreads();

    float a0 = 0.f, a1 = NEGV, a2 = NEGV, a3 = NEGV;
    const int ubase = lane << 2;

    if (tid < 32) {
        a0 = (lane == 0) ? 0.0f : NEGV;
        const int dend = (dstar < PH_) ? dstar : PH_;
        int off = ubase;
        float4 blC = *reinterpret_cast<const float4*>(Bs + off);
        float4 emC = *reinterpret_cast<const float4*>(Es + off);
        for (int d = 1; d <= dend; ++d) {
            const float am1 = __shfl_up_sync(0xffffffffu, a3, 1);
            const float b0 = blC.x, b1 = blC.y, b2 = blC.z, b3 = blC.w;
            const float e0 = emC.x, e1 = emC.y, e2 = emC.z, e3 = emC.w;
            off += DW_;                                     // prefetch next row
            blC = *reinterpret_cast<const float4*>(Bs + off);
            emC = *reinterpret_cast<const float4*>(Es + off);
            const float t0 = a0 + b0, t1 = a1 + b1, t2 = a2 + b2, t3 = a3 + b3;
            const float l0 = am1 + e0, l1 = a0 + e1, l2 = a1 + e2, l3 = a2 + e3;
            const float x0 = fmaxf(t0, l0), x1 = fmaxf(t1, l1);
            const float x2 = fmaxf(t2, l2), x3 = fmaxf(t3, l3);
            const float d0 = fminf(t0, l0) - x0, d1 = fminf(t1, l1) - x1;
            const float d2 = fminf(t2, l2) - x2, d3 = fminf(t3, l3) - x3;
            const float g0 = ex2f_(d0), g1 = ex2f_(d1);
            const float g2 = ex2f_(d2), g3 = ex2f_(d3);
            a0 = x0 + lg2f_(1.0f + g0);
            a1 = x1 + lg2f_(1.0f + g1);
            a2 = x2 + lg2f_(1.0f + g2);
            a3 = x3 + lg2f_(1.0f + g3);
        }
    }
    __syncthreads();

    // Stage phase 1: diagonal rows [PH_, ND_-1), masked + log2-scaled.
    {
        const int base4 = PH_ * DW4_;
        const int m4    = (ND_ - 1 - PH_) * DW4_;    // 147*26
        for (int i = tid; i < m4; i += 128) {
            const int rr = i / DW4_;
            const int r  = PH_ + rr;
            const int v0 = (i - rr * DW4_) * 4;
            stage_row4(gB[base4 + i], gE[base4 + i], r, v0, alen, llen,
                       &sB[i], &sE[i]);
        }
    }
    __syncthreads();

    if (tid < 32) {
        int off = ubase;
        float4 blC = *reinterpret_cast<const float4*>(Bs + off);
        float4 emC = *reinterpret_cast<const float4*>(Es + off);
        for (int d = PH_ + 1; d <= dstar; ++d) {
            const float am1 = __shfl_up_sync(0xffffffffu, a3, 1);
            const float b0 = blC.x, b1 = blC.y, b2 = blC.z, b3 = blC.w;
            const float e0 = emC.x, e1 = emC.y, e2 = emC.z, e3 = emC.w;
            off += DW_;
            blC = *reinterpret_cast<const float4*>(Bs + off);
            emC = *reinterpret_cast<const float4*>(Es + off);
            const float t0 = a0 + b0, t1 = a1 + b1, t2 = a2 + b2, t3 = a3 + b3;
            const float l0 = am1 + e0, l1 = a0 + e1, l2 = a1 + e2, l3 = a2 + e3;
            const float x0 = fmaxf(t0, l0), x1 = fmaxf(t1, l1);
            const float x2 = fmaxf(t2, l2), x3 = fmaxf(t3, l3);
            const float d0 = fminf(t0, l0) - x0, d1 = fminf(t1, l1) - x1;
            const float d2 = fminf(t2, l2) - x2, d3 = fminf(t3, l3) - x3;
            const float g0 = ex2f_(d0), g1 = ex2f_(d1);
            const float g2 = ex2f_(d2), g3 = ex2f_(d3);
            a0 = x0 + lg2f_(1.0f + g0);
            a1 = x1 + lg2f_(1.0f + g1);
            a2 = x2 + lg2f_(1.0f + g2);
            a3 = x3 + lg2f_(1.0f + g3);
        }

        // alpha(alen-1, llen) = a_slot * ln2; final blank read raw from gmem.
        const int slot = llen & 3;
        float r = (slot == 0) ? a0 : (slot == 1) ? a1 : (slot == 2) ? a2 : a3;
        r = __shfl_sync(0xffffffffu, r, llen >> 2);
        if (lane == 0) {
            const float alpha = r * LN2_;
            const float fb = g_blankD[b * ND_ * DW_ + dstar * DW_ + llen];
            g_cost[b] = -(alpha + fb);
            __threadfence();
            const int prev = atomicAdd(&g_done, 1);
            if (prev == B_ - 1) {
                __threadfence();
                float s = 0.0f;
                #pragma unroll
                for (int i = 0; i < B_; ++i) s += g_cost[i];
                out[0] = s / (float)B_;
                g_done = 0;            // reset for next graph replay
            }
        }
    }
}

// ---------------------------------------------------------------------------
extern "C" void kernel_launch(void* const* d_in, const int* in_sizes, int n_in,
                              void* d_out, int out_size)
{
    const float* acts       = (const float*)d_in[0];
    const int*   labels     = (const int*)  d_in[1];
    const int*   act_lens   = (const int*)  d_in[2];
    const int*   label_lens = (const int*)  d_in[3];
    float*       out        = (float*)      d_out;

    // Kernel 1: log-softmax stats over live rows only.
    const int rows   = B_ * T_ * U1_;
    const int wpb    = 8;
    const int blocks = (rows + wpb - 1) / wpb;
    rnnt_softmax_kernel<<<blocks, wpb * 32>>>(acts, labels, act_lens, label_lens);

    // Kernel 2: DP + finalize.
    const size_t smemBytes =
        (size_t)(2 * PH_ * DW_ + PAD_) * sizeof(float);   // 126,976 B
    cudaFuncSetAttribute(rnnt_dp_kernel,
                         cudaFuncAttributeMaxDynamicSharedMemorySize,
                         (int)smemBytes);
    rnnt_dp_kernel<<<B_, 128, smemBytes>>>(act_lens, label_lens, out);
}